// round 10
// baseline (speedup 1.0000x reference)
#include <cuda_runtime.h>

#define NPTS 32768
#define CDIM 128
#define NSAM 16
#define CSD  16
#define PAIRS (NPTS*NSAM)
#define FEPS 1e-5f

// ---------------- scratch (device globals; no allocation allowed) ----------
__device__ float g_q[NPTS*CDIM];
__device__ float g_k[NPTS*CDIM];
__device__ float g_v[NPTS*CDIM];
__device__ float g_prlin[PAIRS*3];
__device__ float g_w2[PAIRS*CSD];

__device__ float g_s1[3],    g_ss1[3],    g_scale1[3],    g_shift1[3];
__device__ float g_s2[CDIM], g_ss2[CDIM], g_scale2[CDIM], g_shift2[CDIM];
__device__ float g_s3[CSD],  g_ss3[CSD],  g_scale3[CSD],  g_shift3[CSD];
__device__ unsigned g_tk1, g_tk2, g_tk3;

__device__ __forceinline__ unsigned f2tf32(float v) {
    unsigned r; asm("cvt.rna.tf32.f32 %0, %1;" : "=r"(r) : "f"(v)); return r;
}
__device__ __forceinline__ void mma_tf32(float* acc, unsigned a0, unsigned a1,
                                         unsigned a2, unsigned a3,
                                         unsigned b0, unsigned b1) {
    asm volatile(
        "mma.sync.aligned.m16n8k8.row.col.f32.tf32.tf32.f32 "
        "{%0,%1,%2,%3}, {%4,%5,%6,%7}, {%8,%9}, {%0,%1,%2,%3};"
        : "+f"(acc[0]), "+f"(acc[1]), "+f"(acc[2]), "+f"(acc[3])
        : "r"(a0), "r"(a1), "r"(a2), "r"(a3), "r"(b0), "r"(b1));
}

// ---------------- K1: q,k,v projections via tf32 mma (v = tf32x3 exact) -----
__global__ __launch_bounds__(128)
void k_proj_mma(const float* __restrict__ x,
                const float* __restrict__ Wq, const float* __restrict__ bq,
                const float* __restrict__ Wk, const float* __restrict__ bk,
                const float* __restrict__ Wv, const float* __restrict__ bv) {
    if (blockIdx.x == 0 && blockIdx.y == 0) {
        int tt = threadIdx.x;
        if (tt < 3)    { g_s1[tt] = 0.f; g_ss1[tt] = 0.f; }
        if (tt < CDIM) { g_s2[tt] = 0.f; g_ss2[tt] = 0.f; }
        if (tt < CSD)  { g_s3[tt] = 0.f; g_ss3[tt] = 0.f; }
        if (tt == 0) { g_tk1 = 0; g_tk2 = 0; g_tk3 = 0; }
    }

    const float* W; const float* b; float* out; bool split;
    if (blockIdx.y == 0)      { W = Wq; b = bq; out = g_q; split = false; }
    else if (blockIdx.y == 1) { W = Wk; b = bk; out = g_k; split = false; }
    else                      { W = Wv; b = bv; out = g_v; split = true;  }

    __shared__ unsigned xs_hi[64*20], xs_lo[64*20];
    __shared__ unsigned ws_hi[128*20], ws_lo[128*20];

    int t = threadIdx.x;
    int lane = t & 31, w = t >> 5;
    int row0 = blockIdx.x * 64;
    int gr = lane >> 2;
    int gc = lane & 3;

    float acc[16][4];
#pragma unroll
    for (int nt = 0; nt < 16; nt++)
#pragma unroll
        for (int j = 0; j < 4; j++) acc[nt][j] = 0.f;

    for (int kb = 0; kb < 128; kb += 16) {
#pragma unroll
        for (int e = t; e < 64*16; e += 128) {
            int r = e >> 4, k = e & 15;
            float xv = x[(row0 + r)*128 + kb + k];
            unsigned hi = f2tf32(xv);
            xs_hi[r*20 + k] = hi;
            if (split) xs_lo[r*20 + k] = f2tf32(xv - __uint_as_float(hi));
        }
#pragma unroll
        for (int e = t; e < 128*16; e += 128) {
            int k = e >> 7, n = e & 127;
            float wv = W[(kb + k)*128 + n];
            unsigned hi = f2tf32(wv);
            ws_hi[n*20 + k] = hi;
            if (split) ws_lo[n*20 + k] = f2tf32(wv - __uint_as_float(hi));
        }
        __syncthreads();

#pragma unroll
        for (int ks = 0; ks < 2; ks++) {
            int k0 = ks*8;
            int ra = (w*16 + gr)*20 + k0 + gc;
            int rb = (w*16 + gr + 8)*20 + k0 + gc;
            unsigned ah0 = xs_hi[ra],     ah1 = xs_hi[rb];
            unsigned ah2 = xs_hi[ra + 4], ah3 = xs_hi[rb + 4];
            unsigned al0 = 0, al1 = 0, al2 = 0, al3 = 0;
            if (split) {
                al0 = xs_lo[ra];     al1 = xs_lo[rb];
                al2 = xs_lo[ra + 4]; al3 = xs_lo[rb + 4];
            }
#pragma unroll
            for (int nt = 0; nt < 16; nt++) {
                int nb = (nt*8 + gr)*20 + k0 + gc;
                unsigned bh0 = ws_hi[nb], bh1 = ws_hi[nb + 4];
                mma_tf32(acc[nt], ah0, ah1, ah2, ah3, bh0, bh1);
                if (split) {
                    unsigned bl0 = ws_lo[nb], bl1 = ws_lo[nb + 4];
                    mma_tf32(acc[nt], al0, al1, al2, al3, bh0, bh1);
                    mma_tf32(acc[nt], ah0, ah1, ah2, ah3, bl0, bl1);
                }
            }
        }
        __syncthreads();
    }

    int r0 = row0 + w*16 + gr;
#pragma unroll
    for (int nt = 0; nt < 16; nt++) {
        int col = nt*8 + gc*2;
        float b0v = b[col], b1v = b[col+1];
        float2 o0 = {acc[nt][0] + b0v, acc[nt][1] + b1v};
        float2 o1 = {acc[nt][2] + b0v, acc[nt][3] + b1v};
        *(float2*)&out[r0*128 + col]     = o0;
        *(float2*)&out[(r0+8)*128 + col] = o1;
    }
}

// ---------------- K2: prlin + BN1 stats + fused finalize --------------------
__global__ void k_prlin(const float* __restrict__ p, const int* __restrict__ idx,
                        const float* __restrict__ pW1, const float* __restrict__ pb1,
                        const float* __restrict__ g, const float* __restrict__ be) {
    float w00 = pW1[0], w01 = pW1[1], w02 = pW1[2];
    float w10 = pW1[3], w11 = pW1[4], w12 = pW1[5];
    float w20 = pW1[6], w21 = pW1[7], w22 = pW1[8];
    float b0 = pb1[0], b1 = pb1[1], b2 = pb1[2];

    float s[3]  = {0.f, 0.f, 0.f};
    float ss[3] = {0.f, 0.f, 0.f};

    int stride = gridDim.x * blockDim.x;
    for (int pair = blockIdx.x*blockDim.x + threadIdx.x; pair < PAIRS; pair += stride) {
        int n   = pair >> 4;
        int nbr = idx[pair];
        float d0 = p[nbr*3+0] - p[n*3+0];
        float d1 = p[nbr*3+1] - p[n*3+1];
        float d2 = p[nbr*3+2] - p[n*3+2];
        float v0 = b0 + d0*w00 + d1*w10 + d2*w20;
        float v1 = b1 + d0*w01 + d1*w11 + d2*w21;
        float v2 = b2 + d0*w02 + d1*w12 + d2*w22;
        g_prlin[pair*3+0] = v0;
        g_prlin[pair*3+1] = v1;
        g_prlin[pair*3+2] = v2;
        s[0] += v0; ss[0] += v0*v0;
        s[1] += v1; ss[1] += v1*v1;
        s[2] += v2; ss[2] += v2*v2;
    }

#pragma unroll
    for (int o = 16; o > 0; o >>= 1) {
#pragma unroll
        for (int j = 0; j < 3; j++) {
            s[j]  += __shfl_down_sync(0xffffffffu, s[j],  o);
            ss[j] += __shfl_down_sync(0xffffffffu, ss[j], o);
        }
    }
    __shared__ float part[8][6];
    int lane = threadIdx.x & 31, w = threadIdx.x >> 5;
    if (lane == 0) {
        part[w][0] = s[0];  part[w][1] = s[1];  part[w][2] = s[2];
        part[w][3] = ss[0]; part[w][4] = ss[1]; part[w][5] = ss[2];
    }
    __syncthreads();
    if (threadIdx.x < 6) {
        float tot = 0.f;
#pragma unroll
        for (int ww = 0; ww < 8; ww++) tot += part[ww][threadIdx.x];
        if (threadIdx.x < 3) atomicAdd(&g_s1[threadIdx.x], tot);
        else                 atomicAdd(&g_ss1[threadIdx.x - 3], tot);
    }
    __syncthreads();
    __shared__ bool is_last;
    if (threadIdx.x == 0) {
        __threadfence();
        is_last = (atomicAdd(&g_tk1, 1u) == gridDim.x - 1);
    }
    __syncthreads();
    if (is_last && threadIdx.x < 3) {
        __threadfence();
        int c = threadIdx.x;
        float cnt = (float)PAIRS;
        float mean = g_s1[c] / cnt;
        float var  = g_ss1[c] / cnt - mean*mean;
        float scv  = g[c] * rsqrtf(var + FEPS);
        g_scale1[c] = scv;
        g_shift1[c] = be[c] - mean*scv;
    }
}

// ---------------- K3: BN2 stats ----------------------------------------------
__global__ __launch_bounds__(256, 5)
void k_bn2stats(const int* __restrict__ idx,
                const float* __restrict__ pW2, const float* __restrict__ pb2,
                const float* __restrict__ g, const float* __restrict__ be) {
    int t = threadIdx.x, lane = t & 31, w = t >> 5;
    int wg = blockIdx.x*8 + w;
    int base = wg*32;

    __shared__ float hsm[8][32][3];
    __shared__ int   ism[8][32];

    float4 pw0  = *(const float4*)&pW2[0*CDIM + lane*4];
    float4 pw1  = *(const float4*)&pW2[1*CDIM + lane*4];
    float4 pw2v = *(const float4*)&pW2[2*CDIM + lane*4];
    float4 pbv  = *(const float4*)&pb2[lane*4];
    float sc0 = g_scale1[0], sc1 = g_scale1[1], sc2 = g_scale1[2];
    float sh0 = g_shift1[0], sh1 = g_shift1[1], sh2 = g_shift1[2];

    {
        int pair = base + lane;
        ism[w][lane] = idx[pair];
        hsm[w][lane][0] = fmaxf(g_prlin[pair*3+0]*sc0 + sh0, 0.f);
        hsm[w][lane][1] = fmaxf(g_prlin[pair*3+1]*sc1 + sh1, 0.f);
        hsm[w][lane][2] = fmaxf(g_prlin[pair*3+2]*sc2 + sh2, 0.f);
    }
    __syncwarp();

    const float4* kp = (const float4*)g_k;
    const float4* qp = (const float4*)g_q;

    float4 s4  = {0.f,0.f,0.f,0.f};
    float4 q4s = {0.f,0.f,0.f,0.f};

#pragma unroll
    for (int np = 0; np < 2; np++) {
        int n = (base >> 4) + np;
        float4 qq = qp[n*32 + lane];
        float4 b4;
        b4.x = pbv.x - qq.x; b4.y = pbv.y - qq.y;
        b4.z = pbv.z - qq.z; b4.w = pbv.w - qq.w;
#pragma unroll
        for (int s = 0; s < 16; s++) {
            int i   = np*16 + s;
            int nbr = ism[w][i];
            float h0 = hsm[w][i][0], h1 = hsm[w][i][1], h2 = hsm[w][i][2];
            float4 kk = kp[nbr*32 + lane];
            float wx = kk.x + b4.x + h0*pw0.x + h1*pw1.x + h2*pw2v.x;
            float wy = kk.y + b4.y + h0*pw0.y + h1*pw1.y + h2*pw2v.y;
            float wz = kk.z + b4.z + h0*pw0.z + h1*pw1.z + h2*pw2v.z;
            float ww = kk.w + b4.w + h0*pw0.w + h1*pw1.w + h2*pw2v.w;
            s4.x += wx; q4s.x += wx*wx;
            s4.y += wy; q4s.y += wy*wy;
            s4.z += wz; q4s.z += wz*wz;
            s4.w += ww; q4s.w += ww*ww;
        }
    }

    __shared__ float red[8][256];
    red[w][lane*4+0]     = s4.x;  red[w][lane*4+1]     = s4.y;
    red[w][lane*4+2]     = s4.z;  red[w][lane*4+3]     = s4.w;
    red[w][128+lane*4+0] = q4s.x; red[w][128+lane*4+1] = q4s.y;
    red[w][128+lane*4+2] = q4s.z; red[w][128+lane*4+3] = q4s.w;
    __syncthreads();
    float tot = 0.f;
#pragma unroll
    for (int ww = 0; ww < 8; ww++) tot += red[ww][t];
    if (t < 128) atomicAdd(&g_s2[t], tot);
    else         atomicAdd(&g_ss2[t-128], tot);

    __syncthreads();
    __shared__ bool is_last;
    if (t == 0) {
        __threadfence();
        is_last = (atomicAdd(&g_tk2, 1u) == gridDim.x - 1);
    }
    __syncthreads();
    if (is_last && t < CDIM) {
        __threadfence();
        float cnt = (float)PAIRS;
        float mean = g_s2[t] / cnt;
        float var  = g_ss2[t] / cnt - mean*mean;
        float scv  = g[t] * rsqrtf(var + FEPS);
        g_scale2[t] = scv;
        g_shift2[t] = be[t] - mean*scv;
    }
}

// ---------------- K4 (PROFILED): w2 pipelined — register-prefetched gather --
// block 256 (8 warps), 4 tiles of 64 pairs per block, grid 2048.
// kk/q prefetched into registers one tile ahead; idx/h prefetched two ahead.
__global__ __launch_bounds__(256, 2)
void k_w2(const int* __restrict__ idx,
          const float* __restrict__ pW2, const float* __restrict__ pb2,
          const float* __restrict__ wW1, const float* __restrict__ wb1,
          const float* __restrict__ g, const float* __restrict__ be) {
    __shared__ unsigned us[64*132];
    __shared__ unsigned wt[16*132];
    __shared__ float hA[8][2][8][3];
    __shared__ int   iA[8][2][8];
    __shared__ float s3s[CSD], ss3s[CSD];

    int t = threadIdx.x, lane = t & 31, w = t >> 5;
    int gr = lane >> 2, gc = lane & 3;

    for (int e = t; e < 128*16; e += 256)
        wt[(e & 15)*132 + (e >> 4)] = f2tf32(wW1[e]);
    if (t < CSD) { s3s[t] = 0.f; ss3s[t] = 0.f; }

    float4 pw0  = *(const float4*)&pW2[0*CDIM + lane*4];
    float4 pw1  = *(const float4*)&pW2[1*CDIM + lane*4];
    float4 pw2v = *(const float4*)&pW2[2*CDIM + lane*4];
    float4 pbv  = *(const float4*)&pb2[lane*4];
    float4 s2c  = *(const float4*)&g_scale2[lane*4];
    float4 h2c  = *(const float4*)&g_shift2[lane*4];
    float sc0 = g_scale1[0], sc1 = g_scale1[1], sc2 = g_scale1[2];
    float sh0 = g_shift1[0], sh1 = g_shift1[1], sh2 = g_shift1[2];

    const float4* kp = (const float4*)g_k;
    const float4* qp = (const float4*)g_q;

    int mt = w >> 1, nt = w & 1;
    int m0 = mt*16;
    int c0 = nt*8 + gc*2;
    float bc0 = wb1[c0], bc1 = wb1[c0+1];

    int tilebase = blockIdx.x*4;

    // prologue: stage idx/h for tiles 0 and 1, prefetch kk/q for tile 0
    if (lane < 8) {
#pragma unroll
        for (int tb = 0; tb < 2; tb++) {
            int pair = (tilebase + tb)*64 + w*8 + lane;
            iA[w][tb][lane] = idx[pair];
            hA[w][tb][lane][0] = fmaxf(g_prlin[pair*3+0]*sc0 + sh0, 0.f);
            hA[w][tb][lane][1] = fmaxf(g_prlin[pair*3+1]*sc1 + sh1, 0.f);
            hA[w][tb][lane][2] = fmaxf(g_prlin[pair*3+2]*sc2 + sh2, 0.f);
        }
    }
    __syncwarp();

    float4 kk_pre[8];
    float4 q_pre;
    {
        int n0 = tilebase*4 + (w >> 1);
        q_pre = qp[n0*32 + lane];
#pragma unroll
        for (int pi = 0; pi < 8; pi++)
            kk_pre[pi] = kp[iA[w][0][pi]*32 + lane];
    }

    float ls0 = 0.f, ls1 = 0.f, lss0 = 0.f, lss1 = 0.f;

    __syncthreads();   // covers wt staging too

    for (int ti = 0; ti < 4; ti++) {
        int tile = tilebase + ti;
        int buf = ti & 1;

        // stage A: compute u from prefetched registers, store to us
        {
            float4 b4;
            b4.x = pbv.x - q_pre.x; b4.y = pbv.y - q_pre.y;
            b4.z = pbv.z - q_pre.z; b4.w = pbv.w - q_pre.w;
#pragma unroll
            for (int pi = 0; pi < 8; pi++) {
                float h0 = hA[w][buf][pi][0];
                float h1 = hA[w][buf][pi][1];
                float h2 = hA[w][buf][pi][2];
                float4 kk = kk_pre[pi];
                uint4 ub;
                ub.x = f2tf32(fmaxf((kk.x + b4.x + h0*pw0.x + h1*pw1.x + h2*pw2v.x)*s2c.x + h2c.x, 0.f));
                ub.y = f2tf32(fmaxf((kk.y + b4.y + h0*pw0.y + h1*pw1.y + h2*pw2v.y)*s2c.y + h2c.y, 0.f));
                ub.z = f2tf32(fmaxf((kk.z + b4.z + h0*pw0.z + h1*pw1.z + h2*pw2v.z)*s2c.z + h2c.z, 0.f));
                ub.w = f2tf32(fmaxf((kk.w + b4.w + h0*pw0.w + h1*pw1.w + h2*pw2v.w)*s2c.w + h2c.w, 0.f));
                *(uint4*)&us[(w*8 + pi)*132 + lane*4] = ub;
            }
        }

        // prefetch kk/q for tile ti+1 (iA[(ti+1)&1] was written last iter / prologue)
        if (ti < 3) {
            int nb = (tile + 1)*4 + (w >> 1);
            q_pre = qp[nb*32 + lane];
#pragma unroll
            for (int pi = 0; pi < 8; pi++)
                kk_pre[pi] = kp[iA[w][(ti+1)&1][pi]*32 + lane];
        }

        // prefetch idx/h for tile ti+2 into buf (hA[buf] already consumed above)
        if (ti < 2 && lane < 8) {
            int pair = (tile + 2)*64 + w*8 + lane;
            iA[w][buf][lane] = idx[pair];
            hA[w][buf][lane][0] = fmaxf(g_prlin[pair*3+0]*sc0 + sh0, 0.f);
            hA[w][buf][lane][1] = fmaxf(g_prlin[pair*3+1]*sc1 + sh1, 0.f);
            hA[w][buf][lane][2] = fmaxf(g_prlin[pair*3+2]*sc2 + sh2, 0.f);
        }

        __syncthreads();

        // stage B: [64x128] @ [128x16] via 16 MMAs per warp
        float acc[4] = {0.f, 0.f, 0.f, 0.f};
        {
            int ra = (m0 + gr)*132 + gc;
            int nb = (nt*8 + gr)*132 + gc;
#pragma unroll
            for (int ks = 0; ks < 16; ks++) {
                unsigned a0 = us[ra],          a1 = us[ra + 8*132];
                unsigned a2 = us[ra + 4],      a3 = us[ra + 8*132 + 4];
                unsigned b0 = wt[nb],          b1 = wt[nb + 4];
                mma_tf32(acc, a0, a1, a2, a3, b0, b1);
                ra += 8; nb += 8;
            }
        }
        float o00 = acc[0] + bc0, o01 = acc[1] + bc1;
        float o10 = acc[2] + bc0, o11 = acc[3] + bc1;
        int pA = tile*64 + m0 + gr;
        int pB = pA + 8;
        float2 oa = {o00, o01}, ob = {o10, o11};
        *(float2*)&g_w2[pA*16 + c0] = oa;
        *(float2*)&g_w2[pB*16 + c0] = ob;
        ls0 += o00 + o10;  lss0 += o00*o00 + o10*o10;
        ls1 += o01 + o11;  lss1 += o01*o01 + o11*o11;
        __syncthreads();
    }

    atomicAdd(&s3s[c0],   ls0);  atomicAdd(&ss3s[c0],   lss0);
    atomicAdd(&s3s[c0+1], ls1);  atomicAdd(&ss3s[c0+1], lss1);
    __syncthreads();
    if (t < CSD)        atomicAdd(&g_s3[t], s3s[t]);
    else if (t < 2*CSD) atomicAdd(&g_ss3[t-CSD], ss3s[t-CSD]);

    __syncthreads();
    __shared__ bool is_last;
    if (t == 0) {
        __threadfence();
        is_last = (atomicAdd(&g_tk3, 1u) == gridDim.x - 1);
    }
    __syncthreads();
    if (is_last && t < CSD) {
        __threadfence();
        float cnt = (float)PAIRS;
        float mean = g_s3[t] / cnt;
        float var  = g_ss3[t] / cnt - mean*mean;
        float scv  = g[t] * rsqrtf(var + FEPS);
        g_scale3[t] = scv;
        g_shift3[t] = be[t] - mean*scv;
    }
}

// ---------------- K5: bn3 + 16x16 matmul + softmax + aggregate --------------
__global__ __launch_bounds__(256)
void k_final(const int* __restrict__ idx,
             const float* __restrict__ pW2, const float* __restrict__ pb2,
             const float* __restrict__ wW2, const float* __restrict__ wb2,
             float* __restrict__ out) {
    int t = threadIdx.x;
    int half = t >> 7;
    int tl = t & 127;
    int n = blockIdx.x*2 + half;

    __shared__ float a[2][16*17];
    __shared__ float wsm[2][16*17];
    __shared__ float hs[2][16][4];
    __shared__ int   nbrs[2][16];
    __shared__ float wW2s[256];

    wW2s[t] = wW2[t];

    if (tl < 16) {
        int pair = n*16 + tl;
        nbrs[half][tl]  = idx[pair];
        hs[half][tl][0] = fmaxf(g_prlin[pair*3+0]*g_scale1[0] + g_shift1[0], 0.f);
        hs[half][tl][1] = fmaxf(g_prlin[pair*3+1]*g_scale1[1] + g_shift1[1], 0.f);
        hs[half][tl][2] = fmaxf(g_prlin[pair*3+2]*g_scale1[2] + g_shift1[2], 0.f);
    }

#pragma unroll
    for (int i = tl; i < 256; i += 128) {
        int c2 = i & 15;
        float v = g_w2[n*256 + i];
        a[half][(i >> 4)*17 + c2] = fmaxf(v*g_scale3[c2] + g_shift3[c2], 0.f);
    }
    __syncthreads();

#pragma unroll
    for (int i = tl; i < 256; i += 128) {
        int s = i >> 4, c2 = i & 15;
        float acc = wb2[c2];
#pragma unroll
        for (int j = 0; j < 16; j++) acc += a[half][s*17 + j] * wW2s[j*16 + c2];
        wsm[half][s*17 + c2] = acc;
    }
    __syncthreads();

    if (tl < 16) {
        float m = -1e30f;
#pragma unroll
        for (int s = 0; s < 16; s++) m = fmaxf(m, wsm[half][s*17 + tl]);
        float e[16]; float sum = 0.f;
#pragma unroll
        for (int s = 0; s < 16; s++) { e[s] = __expf(wsm[half][s*17 + tl] - m); sum += e[s]; }
        float inv = 1.f / sum;
#pragma unroll
        for (int s = 0; s < 16; s++) wsm[half][s*17 + tl] = e[s] * inv;
    }
    __syncthreads();

    int c = tl, c2 = tl & 15;
    float pb2c = pb2[c];
    float pw0 = pW2[c], pw1 = pW2[128 + c], pw2 = pW2[256 + c];
    float acc = 0.f;
#pragma unroll
    for (int s = 0; s < 16; s++) {
        float vv  = g_v[nbrs[half][s]*128 + c];
        float pr1 = pb2c + hs[half][s][0]*pw0 + hs[half][s][1]*pw1 + hs[half][s][2]*pw2;
        acc += (vv + pr1) * wsm[half][s*17 + c2];
    }
    out[n*128 + c] = acc;
}

// ---------------- launch -----------------------------------------------------
extern "C" void kernel_launch(void* const* d_in, const int* in_sizes, int n_in,
                              void* d_out, int out_size) {
    (void)in_sizes; (void)n_in; (void)out_size;
    const float* p    = (const float*)d_in[0];
    const float* x    = (const float*)d_in[1];
    const float* Wq   = (const float*)d_in[2];
    const float* bq   = (const float*)d_in[3];
    const float* Wk   = (const float*)d_in[4];
    const float* bk   = (const float*)d_in[5];
    const float* Wv   = (const float*)d_in[6];
    const float* bv   = (const float*)d_in[7];
    const float* pW1  = (const float*)d_in[8];
    const float* pb1  = (const float*)d_in[9];
    const float* pg1  = (const float*)d_in[10];
    const float* pbe1 = (const float*)d_in[11];
    const float* pW2  = (const float*)d_in[12];
    const float* pb2  = (const float*)d_in[13];
    const float* wg1  = (const float*)d_in[14];
    const float* wbe1 = (const float*)d_in[15];
    const float* wW1  = (const float*)d_in[16];
    const float* wb1  = (const float*)d_in[17];
    const float* wg2  = (const float*)d_in[18];
    const float* wbe2 = (const float*)d_in[19];
    const float* wW2  = (const float*)d_in[20];
    const float* wb2  = (const float*)d_in[21];
    const int*   idx  = (const int*)  d_in[22];
    float* out = (float*)d_out;

    k_proj_mma<<<dim3(NPTS/64, 3), 128>>>(x, Wq, bq, Wk, bk, Wv, bv);    // 1 (+zero)
    k_prlin<<<512, 256>>>(p, idx, pW1, pb1, pg1, pbe1);                  // 2
    k_bn2stats<<<2048, 256>>>(idx, pW2, pb2, wg1, wbe1);                 // 3
    k_w2<<<2048, 256>>>(idx, pW2, pb2, wW1, wb1, wg2, wbe2);             // 4 <- profiled
    k_final<<<NPTS/2, 256>>>(idx, pW2, pb2, wW2, wb2, out);              // 5
}

// round 11
// speedup vs baseline: 1.0399x; 1.0399x over previous
#include <cuda_runtime.h>

#define NPTS 32768
#define CDIM 128
#define NSAM 16
#define CSD  16
#define PAIRS (NPTS*NSAM)
#define FEPS 1e-5f

// ---------------- scratch (device globals; no allocation allowed) ----------
__device__ float g_q[NPTS*CDIM];
__device__ float g_k[NPTS*CDIM];
__device__ float g_v[NPTS*CDIM];
__device__ float g_prlin[PAIRS*3];
__device__ float g_w2[PAIRS*CSD];

__device__ float g_s1[3],    g_ss1[3],    g_scale1[3],    g_shift1[3];
__device__ float g_s2[CDIM], g_ss2[CDIM], g_scale2[CDIM], g_shift2[CDIM];
__device__ float g_s3[CSD],  g_ss3[CSD],  g_scale3[CSD],  g_shift3[CSD];
__device__ unsigned g_tk1, g_tk2, g_tk3;

__device__ __forceinline__ unsigned f2tf32(float v) {
    unsigned r; asm("cvt.rna.tf32.f32 %0, %1;" : "=r"(r) : "f"(v)); return r;
}
__device__ __forceinline__ void mma_tf32(float* acc, unsigned a0, unsigned a1,
                                         unsigned a2, unsigned a3,
                                         unsigned b0, unsigned b1) {
    asm volatile(
        "mma.sync.aligned.m16n8k8.row.col.f32.tf32.tf32.f32 "
        "{%0,%1,%2,%3}, {%4,%5,%6,%7}, {%8,%9}, {%0,%1,%2,%3};"
        : "+f"(acc[0]), "+f"(acc[1]), "+f"(acc[2]), "+f"(acc[3])
        : "r"(a0), "r"(a1), "r"(a2), "r"(a3), "r"(b0), "r"(b1));
}

// ---------------- K1: q,k,v projections via tf32 mma (v = tf32x3 exact) -----
__global__ __launch_bounds__(128)
void k_proj_mma(const float* __restrict__ x,
                const float* __restrict__ Wq, const float* __restrict__ bq,
                const float* __restrict__ Wk, const float* __restrict__ bk,
                const float* __restrict__ Wv, const float* __restrict__ bv) {
    if (blockIdx.x == 0 && blockIdx.y == 0) {
        int tt = threadIdx.x;
        if (tt < 3)    { g_s1[tt] = 0.f; g_ss1[tt] = 0.f; }
        if (tt < CDIM) { g_s2[tt] = 0.f; g_ss2[tt] = 0.f; }
        if (tt < CSD)  { g_s3[tt] = 0.f; g_ss3[tt] = 0.f; }
        if (tt == 0) { g_tk1 = 0; g_tk2 = 0; g_tk3 = 0; }
    }

    const float* W; const float* b; float* out; bool split;
    if (blockIdx.y == 0)      { W = Wq; b = bq; out = g_q; split = false; }
    else if (blockIdx.y == 1) { W = Wk; b = bk; out = g_k; split = false; }
    else                      { W = Wv; b = bv; out = g_v; split = true;  }

    __shared__ unsigned xs_hi[64*20], xs_lo[64*20];
    __shared__ unsigned ws_hi[128*20], ws_lo[128*20];

    int t = threadIdx.x;
    int lane = t & 31, w = t >> 5;
    int row0 = blockIdx.x * 64;
    int gr = lane >> 2;
    int gc = lane & 3;

    float acc[16][4];
#pragma unroll
    for (int nt = 0; nt < 16; nt++)
#pragma unroll
        for (int j = 0; j < 4; j++) acc[nt][j] = 0.f;

    for (int kb = 0; kb < 128; kb += 16) {
#pragma unroll
        for (int e = t; e < 64*16; e += 128) {
            int r = e >> 4, k = e & 15;
            float xv = x[(row0 + r)*128 + kb + k];
            unsigned hi = f2tf32(xv);
            xs_hi[r*20 + k] = hi;
            if (split) xs_lo[r*20 + k] = f2tf32(xv - __uint_as_float(hi));
        }
#pragma unroll
        for (int e = t; e < 128*16; e += 128) {
            int k = e >> 7, n = e & 127;
            float wv = W[(kb + k)*128 + n];
            unsigned hi = f2tf32(wv);
            ws_hi[n*20 + k] = hi;
            if (split) ws_lo[n*20 + k] = f2tf32(wv - __uint_as_float(hi));
        }
        __syncthreads();

#pragma unroll
        for (int ks = 0; ks < 2; ks++) {
            int k0 = ks*8;
            int ra = (w*16 + gr)*20 + k0 + gc;
            int rb = (w*16 + gr + 8)*20 + k0 + gc;
            unsigned ah0 = xs_hi[ra],     ah1 = xs_hi[rb];
            unsigned ah2 = xs_hi[ra + 4], ah3 = xs_hi[rb + 4];
            unsigned al0 = 0, al1 = 0, al2 = 0, al3 = 0;
            if (split) {
                al0 = xs_lo[ra];     al1 = xs_lo[rb];
                al2 = xs_lo[ra + 4]; al3 = xs_lo[rb + 4];
            }
#pragma unroll
            for (int nt = 0; nt < 16; nt++) {
                int nb = (nt*8 + gr)*20 + k0 + gc;
                unsigned bh0 = ws_hi[nb], bh1 = ws_hi[nb + 4];
                mma_tf32(acc[nt], ah0, ah1, ah2, ah3, bh0, bh1);
                if (split) {
                    unsigned bl0 = ws_lo[nb], bl1 = ws_lo[nb + 4];
                    mma_tf32(acc[nt], al0, al1, al2, al3, bh0, bh1);
                    mma_tf32(acc[nt], ah0, ah1, ah2, ah3, bl0, bl1);
                }
            }
        }
        __syncthreads();
    }

    int r0 = row0 + w*16 + gr;
#pragma unroll
    for (int nt = 0; nt < 16; nt++) {
        int col = nt*8 + gc*2;
        float b0v = b[col], b1v = b[col+1];
        float2 o0 = {acc[nt][0] + b0v, acc[nt][1] + b1v};
        float2 o1 = {acc[nt][2] + b0v, acc[nt][3] + b1v};
        *(float2*)&out[r0*128 + col]     = o0;
        *(float2*)&out[(r0+8)*128 + col] = o1;
    }
}

// ---------------- K2: prlin + BN1 stats + fused finalize --------------------
__global__ void k_prlin(const float* __restrict__ p, const int* __restrict__ idx,
                        const float* __restrict__ pW1, const float* __restrict__ pb1,
                        const float* __restrict__ g, const float* __restrict__ be) {
    float w00 = pW1[0], w01 = pW1[1], w02 = pW1[2];
    float w10 = pW1[3], w11 = pW1[4], w12 = pW1[5];
    float w20 = pW1[6], w21 = pW1[7], w22 = pW1[8];
    float b0 = pb1[0], b1 = pb1[1], b2 = pb1[2];

    float s[3]  = {0.f, 0.f, 0.f};
    float ss[3] = {0.f, 0.f, 0.f};

    int stride = gridDim.x * blockDim.x;
    for (int pair = blockIdx.x*blockDim.x + threadIdx.x; pair < PAIRS; pair += stride) {
        int n   = pair >> 4;
        int nbr = idx[pair];
        float d0 = p[nbr*3+0] - p[n*3+0];
        float d1 = p[nbr*3+1] - p[n*3+1];
        float d2 = p[nbr*3+2] - p[n*3+2];
        float v0 = b0 + d0*w00 + d1*w10 + d2*w20;
        float v1 = b1 + d0*w01 + d1*w11 + d2*w21;
        float v2 = b2 + d0*w02 + d1*w12 + d2*w22;
        g_prlin[pair*3+0] = v0;
        g_prlin[pair*3+1] = v1;
        g_prlin[pair*3+2] = v2;
        s[0] += v0; ss[0] += v0*v0;
        s[1] += v1; ss[1] += v1*v1;
        s[2] += v2; ss[2] += v2*v2;
    }

#pragma unroll
    for (int o = 16; o > 0; o >>= 1) {
#pragma unroll
        for (int j = 0; j < 3; j++) {
            s[j]  += __shfl_down_sync(0xffffffffu, s[j],  o);
            ss[j] += __shfl_down_sync(0xffffffffu, ss[j], o);
        }
    }
    __shared__ float part[8][6];
    int lane = threadIdx.x & 31, w = threadIdx.x >> 5;
    if (lane == 0) {
        part[w][0] = s[0];  part[w][1] = s[1];  part[w][2] = s[2];
        part[w][3] = ss[0]; part[w][4] = ss[1]; part[w][5] = ss[2];
    }
    __syncthreads();
    if (threadIdx.x < 6) {
        float tot = 0.f;
#pragma unroll
        for (int ww = 0; ww < 8; ww++) tot += part[ww][threadIdx.x];
        if (threadIdx.x < 3) atomicAdd(&g_s1[threadIdx.x], tot);
        else                 atomicAdd(&g_ss1[threadIdx.x - 3], tot);
    }
    __syncthreads();
    __shared__ bool is_last;
    if (threadIdx.x == 0) {
        __threadfence();
        is_last = (atomicAdd(&g_tk1, 1u) == gridDim.x - 1);
    }
    __syncthreads();
    if (is_last && threadIdx.x < 3) {
        __threadfence();
        int c = threadIdx.x;
        float cnt = (float)PAIRS;
        float mean = g_s1[c] / cnt;
        float var  = g_ss1[c] / cnt - mean*mean;
        float scv  = g[c] * rsqrtf(var + FEPS);
        g_scale1[c] = scv;
        g_shift1[c] = be[c] - mean*scv;
    }
}

// ---------------- K3: BN2 stats ----------------------------------------------
__global__ __launch_bounds__(256, 5)
void k_bn2stats(const int* __restrict__ idx,
                const float* __restrict__ pW2, const float* __restrict__ pb2,
                const float* __restrict__ g, const float* __restrict__ be) {
    int t = threadIdx.x, lane = t & 31, w = t >> 5;
    int wg = blockIdx.x*8 + w;
    int base = wg*32;

    __shared__ float hsm[8][32][3];
    __shared__ int   ism[8][32];

    float4 pw0  = *(const float4*)&pW2[0*CDIM + lane*4];
    float4 pw1  = *(const float4*)&pW2[1*CDIM + lane*4];
    float4 pw2v = *(const float4*)&pW2[2*CDIM + lane*4];
    float4 pbv  = *(const float4*)&pb2[lane*4];
    float sc0 = g_scale1[0], sc1 = g_scale1[1], sc2 = g_scale1[2];
    float sh0 = g_shift1[0], sh1 = g_shift1[1], sh2 = g_shift1[2];

    {
        int pair = base + lane;
        ism[w][lane] = idx[pair];
        hsm[w][lane][0] = fmaxf(g_prlin[pair*3+0]*sc0 + sh0, 0.f);
        hsm[w][lane][1] = fmaxf(g_prlin[pair*3+1]*sc1 + sh1, 0.f);
        hsm[w][lane][2] = fmaxf(g_prlin[pair*3+2]*sc2 + sh2, 0.f);
    }
    __syncwarp();

    const float4* kp = (const float4*)g_k;
    const float4* qp = (const float4*)g_q;

    float4 s4  = {0.f,0.f,0.f,0.f};
    float4 q4s = {0.f,0.f,0.f,0.f};

#pragma unroll
    for (int np = 0; np < 2; np++) {
        int n = (base >> 4) + np;
        float4 qq = qp[n*32 + lane];
        float4 b4;
        b4.x = pbv.x - qq.x; b4.y = pbv.y - qq.y;
        b4.z = pbv.z - qq.z; b4.w = pbv.w - qq.w;
#pragma unroll
        for (int s = 0; s < 16; s++) {
            int i   = np*16 + s;
            int nbr = ism[w][i];
            float h0 = hsm[w][i][0], h1 = hsm[w][i][1], h2 = hsm[w][i][2];
            float4 kk = kp[nbr*32 + lane];
            float wx = kk.x + b4.x + h0*pw0.x + h1*pw1.x + h2*pw2v.x;
            float wy = kk.y + b4.y + h0*pw0.y + h1*pw1.y + h2*pw2v.y;
            float wz = kk.z + b4.z + h0*pw0.z + h1*pw1.z + h2*pw2v.z;
            float ww = kk.w + b4.w + h0*pw0.w + h1*pw1.w + h2*pw2v.w;
            s4.x += wx; q4s.x += wx*wx;
            s4.y += wy; q4s.y += wy*wy;
            s4.z += wz; q4s.z += wz*wz;
            s4.w += ww; q4s.w += ww*ww;
        }
    }

    __shared__ float red[8][256];
    red[w][lane*4+0]     = s4.x;  red[w][lane*4+1]     = s4.y;
    red[w][lane*4+2]     = s4.z;  red[w][lane*4+3]     = s4.w;
    red[w][128+lane*4+0] = q4s.x; red[w][128+lane*4+1] = q4s.y;
    red[w][128+lane*4+2] = q4s.z; red[w][128+lane*4+3] = q4s.w;
    __syncthreads();
    float tot = 0.f;
#pragma unroll
    for (int ww = 0; ww < 8; ww++) tot += red[ww][t];
    if (t < 128) atomicAdd(&g_s2[t], tot);
    else         atomicAdd(&g_ss2[t-128], tot);

    __syncthreads();
    __shared__ bool is_last;
    if (t == 0) {
        __threadfence();
        is_last = (atomicAdd(&g_tk2, 1u) == gridDim.x - 1);
    }
    __syncthreads();
    if (is_last && t < CDIM) {
        __threadfence();
        float cnt = (float)PAIRS;
        float mean = g_s2[t] / cnt;
        float var  = g_ss2[t] / cnt - mean*mean;
        float scv  = g[t] * rsqrtf(var + FEPS);
        g_scale2[t] = scv;
        g_shift2[t] = be[t] - mean*scv;
    }
}

// ---------------- K4 (PROFILED): w2 warp-autonomous — no block barriers -----
// block 128 (4 warps), each warp owns 4 points (16 pairs each), grid 2048.
// Per point: gather+u into private smem tile, __syncwarp, 32 MMAs. No
// __syncthreads in the main loop.
__global__ __launch_bounds__(128, 5)
void k_w2(const int* __restrict__ idx,
          const float* __restrict__ pW2, const float* __restrict__ pb2,
          const float* __restrict__ wW1, const float* __restrict__ wb1,
          const float* __restrict__ g, const float* __restrict__ be) {
    __shared__ unsigned us[4*16*132];     // per-warp 16x128 u tile (stride 132)
    __shared__ unsigned wt[16*132];       // wW1^T tf32 bits, [j][c]
    __shared__ float hA[4][16][3];
    __shared__ int   iA[4][16];
    __shared__ float s3s[CSD], ss3s[CSD];

    int t = threadIdx.x, lane = t & 31, w = t >> 5;   // w: 0..3
    int gr = lane >> 2, gc = lane & 3;

    for (int e = t; e < 128*16; e += 128)
        wt[(e & 15)*132 + (e >> 4)] = f2tf32(wW1[e]);
    if (t < CSD) { s3s[t] = 0.f; ss3s[t] = 0.f; }

    float4 pw0  = *(const float4*)&pW2[0*CDIM + lane*4];
    float4 pw1  = *(const float4*)&pW2[1*CDIM + lane*4];
    float4 pw2v = *(const float4*)&pW2[2*CDIM + lane*4];
    float4 pbv  = *(const float4*)&pb2[lane*4];
    float4 s2c  = *(const float4*)&g_scale2[lane*4];
    float4 h2c  = *(const float4*)&g_shift2[lane*4];
    float sc0 = g_scale1[0], sc1 = g_scale1[1], sc2 = g_scale1[2];
    float sh0 = g_shift1[0], sh1 = g_shift1[1], sh2 = g_shift1[2];

    const float4* kp = (const float4*)g_k;
    const float4* qp = (const float4*)g_q;

    // output cols this thread owns (2 per n-tile): stats accumulators
    float bcol[4];
    bcol[0] = wb1[gc*2];     bcol[1] = wb1[gc*2+1];
    bcol[2] = wb1[8+gc*2];   bcol[3] = wb1[8+gc*2+1];
    float ls[4]  = {0.f,0.f,0.f,0.f};
    float lss[4] = {0.f,0.f,0.f,0.f};

    unsigned* usw = &us[w*16*132];

    __syncthreads();   // wt + s3s ready (only block-wide sync before epilogue)

    for (int pt = 0; pt < 4; pt++) {
        int n = blockIdx.x*16 + w*4 + pt;

        // stage h + idx for this point's 16 pairs (lanes 0-15)
        if (lane < 16) {
            int pair = n*16 + lane;
            iA[w][lane] = idx[pair];
            hA[w][lane][0] = fmaxf(g_prlin[pair*3+0]*sc0 + sh0, 0.f);
            hA[w][lane][1] = fmaxf(g_prlin[pair*3+1]*sc1 + sh1, 0.f);
            hA[w][lane][2] = fmaxf(g_prlin[pair*3+2]*sc2 + sh2, 0.f);
        }
        __syncwarp();

        // gather + u build (16 pairs, all lanes)
        {
            float4 qq = qp[n*32 + lane];
            float4 b4;
            b4.x = pbv.x - qq.x; b4.y = pbv.y - qq.y;
            b4.z = pbv.z - qq.z; b4.w = pbv.w - qq.w;
#pragma unroll
            for (int pi = 0; pi < 16; pi++) {
                int nbr = iA[w][pi];
                float h0 = hA[w][pi][0], h1 = hA[w][pi][1], h2 = hA[w][pi][2];
                float4 kk = kp[nbr*32 + lane];
                uint4 ub;
                ub.x = f2tf32(fmaxf((kk.x + b4.x + h0*pw0.x + h1*pw1.x + h2*pw2v.x)*s2c.x + h2c.x, 0.f));
                ub.y = f2tf32(fmaxf((kk.y + b4.y + h0*pw0.y + h1*pw1.y + h2*pw2v.y)*s2c.y + h2c.y, 0.f));
                ub.z = f2tf32(fmaxf((kk.z + b4.z + h0*pw0.z + h1*pw1.z + h2*pw2v.z)*s2c.z + h2c.z, 0.f));
                ub.w = f2tf32(fmaxf((kk.w + b4.w + h0*pw0.w + h1*pw1.w + h2*pw2v.w)*s2c.w + h2c.w, 0.f));
                *(uint4*)&usw[pi*132 + lane*4] = ub;
            }
        }
        __syncwarp();

        // MMA: u[16x128] @ wW1[128x16] -> 16x16, 2 n-tiles x 16 k-steps
#pragma unroll
        for (int nt2 = 0; nt2 < 2; nt2++) {
            float acc[4] = {0.f, 0.f, 0.f, 0.f};
            int ra = gr*132 + gc;
            int nb = (nt2*8 + gr)*132 + gc;
#pragma unroll
            for (int ks = 0; ks < 16; ks++) {
                unsigned a0 = usw[ra],     a1 = usw[ra + 8*132];
                unsigned a2 = usw[ra + 4], a3 = usw[ra + 8*132 + 4];
                unsigned b0 = wt[nb],      b1 = wt[nb + 4];
                mma_tf32(acc, a0, a1, a2, a3, b0, b1);
                ra += 8; nb += 8;
            }
            int c0 = nt2*8 + gc*2;
            float o00 = acc[0] + bcol[nt2*2+0], o01 = acc[1] + bcol[nt2*2+1];
            float o10 = acc[2] + bcol[nt2*2+0], o11 = acc[3] + bcol[nt2*2+1];
            int pA = n*16 + gr;
            int pB = pA + 8;
            float2 oa = {o00, o01}, ob = {o10, o11};
            *(float2*)&g_w2[pA*16 + c0] = oa;
            *(float2*)&g_w2[pB*16 + c0] = ob;
            ls[nt2*2+0] += o00 + o10;  lss[nt2*2+0] += o00*o00 + o10*o10;
            ls[nt2*2+1] += o01 + o11;  lss[nt2*2+1] += o01*o01 + o11*o11;
        }
        __syncwarp();
    }

    // BN3 stats reduction
    atomicAdd(&s3s[gc*2],     ls[0]);  atomicAdd(&ss3s[gc*2],     lss[0]);
    atomicAdd(&s3s[gc*2+1],   ls[1]);  atomicAdd(&ss3s[gc*2+1],   lss[1]);
    atomicAdd(&s3s[8+gc*2],   ls[2]);  atomicAdd(&ss3s[8+gc*2],   lss[2]);
    atomicAdd(&s3s[8+gc*2+1], ls[3]);  atomicAdd(&ss3s[8+gc*2+1], lss[3]);
    __syncthreads();
    if (t < CSD)        atomicAdd(&g_s3[t], s3s[t]);
    else if (t < 2*CSD) atomicAdd(&g_ss3[t-CSD], ss3s[t-CSD]);

    __syncthreads();
    __shared__ bool is_last;
    if (t == 0) {
        __threadfence();
        is_last = (atomicAdd(&g_tk3, 1u) == gridDim.x - 1);
    }
    __syncthreads();
    if (is_last && t < CSD) {
        __threadfence();
        float cnt = (float)PAIRS;
        float mean = g_s3[t] / cnt;
        float var  = g_ss3[t] / cnt - mean*mean;
        float scv  = g[t] * rsqrtf(var + FEPS);
        g_scale3[t] = scv;
        g_shift3[t] = be[t] - mean*scv;
    }
}

// ---------------- K5: bn3 + 16x16 matmul + softmax + aggregate --------------
__global__ __launch_bounds__(256)
void k_final(const int* __restrict__ idx,
             const float* __restrict__ pW2, const float* __restrict__ pb2,
             const float* __restrict__ wW2, const float* __restrict__ wb2,
             float* __restrict__ out) {
    int t = threadIdx.x;
    int half = t >> 7;
    int tl = t & 127;
    int n = blockIdx.x*2 + half;

    __shared__ float a[2][16*17];
    __shared__ float wsm[2][16*17];
    __shared__ float hs[2][16][4];
    __shared__ int   nbrs[2][16];
    __shared__ float wW2s[256];

    wW2s[t] = wW2[t];

    if (tl < 16) {
        int pair = n*16 + tl;
        nbrs[half][tl]  = idx[pair];
        hs[half][tl][0] = fmaxf(g_prlin[pair*3+0]*g_scale1[0] + g_shift1[0], 0.f);
        hs[half][tl][1] = fmaxf(g_prlin[pair*3+1]*g_scale1[1] + g_shift1[1], 0.f);
        hs[half][tl][2] = fmaxf(g_prlin[pair*3+2]*g_scale1[2] + g_shift1[2], 0.f);
    }

#pragma unroll
    for (int i = tl; i < 256; i += 128) {
        int c2 = i & 15;
        float v = g_w2[n*256 + i];
        a[half][(i >> 4)*17 + c2] = fmaxf(v*g_scale3[c2] + g_shift3[c2], 0.f);
    }
    __syncthreads();

#pragma unroll
    for (int i = tl; i < 256; i += 128) {
        int s = i >> 4, c2 = i & 15;
        float acc = wb2[c2];
#pragma unroll
        for (int j = 0; j < 16; j++) acc += a[half][s*17 + j] * wW2s[j*16 + c2];
        wsm[half][s*17 + c2] = acc;
    }
    __syncthreads();

    if (tl < 16) {
        float m = -1e30f;
#pragma unroll
        for (int s = 0; s < 16; s++) m = fmaxf(m, wsm[half][s*17 + tl]);
        float e[16]; float sum = 0.f;
#pragma unroll
        for (int s = 0; s < 16; s++) { e[s] = __expf(wsm[half][s*17 + tl] - m); sum += e[s]; }
        float inv = 1.f / sum;
#pragma unroll
        for (int s = 0; s < 16; s++) wsm[half][s*17 + tl] = e[s] * inv;
    }
    __syncthreads();

    int c = tl, c2 = tl & 15;
    float pb2c = pb2[c];
    float pw0 = pW2[c], pw1 = pW2[128 + c], pw2 = pW2[256 + c];
    float acc = 0.f;
#pragma unroll
    for (int s = 0; s < 16; s++) {
        float vv  = g_v[nbrs[half][s]*128 + c];
        float pr1 = pb2c + hs[half][s][0]*pw0 + hs[half][s][1]*pw1 + hs[half][s][2]*pw2;
        acc += (vv + pr1) * wsm[half][s*17 + c2];
    }
    out[n*128 + c] = acc;
}

// ---------------- launch -----------------------------------------------------
extern "C" void kernel_launch(void* const* d_in, const int* in_sizes, int n_in,
                              void* d_out, int out_size) {
    (void)in_sizes; (void)n_in; (void)out_size;
    const float* p    = (const float*)d_in[0];
    const float* x    = (const float*)d_in[1];
    const float* Wq   = (const float*)d_in[2];
    const float* bq   = (const float*)d_in[3];
    const float* Wk   = (const float*)d_in[4];
    const float* bk   = (const float*)d_in[5];
    const float* Wv   = (const float*)d_in[6];
    const float* bv   = (const float*)d_in[7];
    const float* pW1  = (const float*)d_in[8];
    const float* pb1  = (const float*)d_in[9];
    const float* pg1  = (const float*)d_in[10];
    const float* pbe1 = (const float*)d_in[11];
    const float* pW2  = (const float*)d_in[12];
    const float* pb2  = (const float*)d_in[13];
    const float* wg1  = (const float*)d_in[14];
    const float* wbe1 = (const float*)d_in[15];
    const float* wW1  = (const float*)d_in[16];
    const float* wb1  = (const float*)d_in[17];
    const float* wg2  = (const float*)d_in[18];
    const float* wbe2 = (const float*)d_in[19];
    const float* wW2  = (const float*)d_in[20];
    const float* wb2  = (const float*)d_in[21];
    const int*   idx  = (const int*)  d_in[22];
    float* out = (float*)d_out;

    k_proj_mma<<<dim3(NPTS/64, 3), 128>>>(x, Wq, bq, Wk, bk, Wv, bv);    // 1 (+zero)
    k_prlin<<<512, 256>>>(p, idx, pW1, pb1, pg1, pbe1);                  // 2
    k_bn2stats<<<2048, 256>>>(idx, pW2, pb2, wg1, wbe1);                 // 3
    k_w2<<<2048, 128>>>(idx, pW2, pb2, wW1, wb1, wg2, wbe2);             // 4 <- profiled
    k_final<<<NPTS/2, 256>>>(idx, pW2, pb2, wW2, wb2, out);              // 5
}